// round 10
// baseline (speedup 1.0000x reference)
#include <cuda_runtime.h>

// DendriticLayer: B=512, N_IN=1024, N_OUT=256, T=100, dt=1.
// Event-scatter formulation (R8/R9) + latency-shaped body (R10):
//   delta[ceil(s_j)] += 0.1*K2*w_j*exp((s_j-ceil(s_j))/5)   (private SMEM col)
//   Chat_t = d*Chat_{t-1} + delta_t ;  w_t = 0.9*w_{t-1} + Chat_t  (w = K2*v)
//   e_t = exp2(w_t);  out = (sum t*e_t)/(sum e_t)
// R10 changes: prefetched LDS.128 (next chunk loaded before current consumed),
// MUFU consumers deferred to end of chunk, dual accumulators, and phase-1
// zeroing folded into the phase-0 body (store zero to dead chunk after read).

#define CH0 13   // phase-0: 52 steps (t in [0,52))
#define CH1 12   // phase-1: 48 steps (t in [52,100))

__device__ __forceinline__ float ex2(float x) {
    float y;
    asm("ex2.approx.ftz.f32 %0, %1;" : "=f"(y) : "f"(x));
    return y;
}

constexpr float D1f = 0.81873075307798185867f;  // exp(-0.2)
constexpr float K2f = 2.8853900817779268147f;   // 2*log2(e)

struct Acc { float C, w, S0, S1, W0, W1; };

// Process one 4-step chunk: recurrence + MUFUs first, accumulates last.
template <int T>
__device__ __forceinline__ void chunk4(Acc& a, const float4 d4) {
    const float C0 = fmaf(a.C, D1f, d4.x);
    const float w0 = fmaf(a.w, 0.9f, C0);
    const float e0 = ex2(w0);
    const float C1 = fmaf(C0, D1f, d4.y);
    const float w1 = fmaf(w0, 0.9f, C1);
    const float e1 = ex2(w1);
    const float C2 = fmaf(C1, D1f, d4.z);
    const float w2 = fmaf(w1, 0.9f, C2);
    const float e2 = ex2(w2);
    const float C3 = fmaf(C2, D1f, d4.w);
    const float w3 = fmaf(w2, 0.9f, C3);
    const float e3 = ex2(w3);
    a.C = C3; a.w = w3;
    // consumers deferred: e0 is ~10 instrs past its MUFU by now
    a.S0 += e0;  a.W0 = fmaf(e0, (float)(T + 0), a.W0);
    a.S1 += e1;  a.W1 = fmaf(e1, (float)(T + 1), a.W1);
    a.S0 += e2;  a.W0 = fmaf(e2, (float)(T + 2), a.W0);
    a.S1 += e3;  a.W1 = fmaf(e3, (float)(T + 3), a.W1);
}

// Pipelined run: d4 holds chunk K (prefetched); load K+1 before consuming K.
// If REZERO, store zero back to chunk K after its load is consumed (dead slot,
// needed cleared for phase 1).
template <int T0, int NCH, int K, bool REZERO>
__device__ __forceinline__ void run(Acc& a, float4* __restrict__ col, float4 d4) {
    float4 nxt;
    if constexpr (K + 1 < NCH) nxt = col[(K + 1) * 128];     // prefetch
    if constexpr (REZERO) {
        if constexpr (K < CH1) col[K * 128] = make_float4(0.f, 0.f, 0.f, 0.f);
    }
    chunk4<T0 + 4 * K>(a, d4);
    if constexpr (K + 1 < NCH) run<T0, NCH, K + 1, REZERO>(a, col, nxt);
}

__global__ __launch_bounds__(128)
void dendritic_kernel(const float* __restrict__ spikes,  // [512,1024]
                      const float* __restrict__ W,       // [256,1024]
                      float* __restrict__ out)           // [512,256]
{
    __shared__ float4 tbl[CH0][128];                     // 26.6KB

    const int tid = threadIdx.x;
    const int idx = blockIdx.x * 128 + tid;              // b*256 + o
    const int o   = idx & 255;

    const float4 s4 = reinterpret_cast<const float4*>(spikes)[idx];
    const float4 w4 = reinterpret_cast<const float4*>(W)[257 * o];

    const float e0 = ceilf(s4.x), e1 = ceilf(s4.y), e2 = ceilf(s4.z), e3 = ceilf(s4.w);
    const float kk = 0.1f * K2f;
    const float c0 = kk * w4.x * __expf(0.2f * (s4.x - e0));
    const float c1 = kk * w4.y * __expf(0.2f * (s4.y - e1));
    const float c2 = kk * w4.z * __expf(0.2f * (s4.z - e2));
    const float c3 = kk * w4.w * __expf(0.2f * (s4.w - e3));
    const int i0 = (int)e0, i1 = (int)e1, i2 = (int)e2, i3 = (int)e3;

    float* tf = reinterpret_cast<float*>(tbl);
    const int tb = tid * 4;
    #define SLOT(k) (((k) >> 2) * 512 + tb + ((k) & 3))

    float4* col = &tbl[0][tid];
    Acc a; a.C = 0.f; a.w = 0.f; a.S0 = 0.f; a.S1 = 0.f; a.W0 = 0.f; a.W1 = 0.f;

    // ---- phase 0: zero, scatter events with e < 52, run (re-zeroing inline) ----
    #pragma unroll
    for (int c = 0; c < CH0; ++c) tbl[c][tid] = make_float4(0.f, 0.f, 0.f, 0.f);
    if (i0 < 52) tf[SLOT(i0)] += c0;       // thread-private column: race-free
    if (i1 < 52) tf[SLOT(i1)] += c1;
    if (i2 < 52) tf[SLOT(i2)] += c2;
    if (i3 < 52) tf[SLOT(i3)] += c3;
    run<0, CH0, 0, true>(a, col, col[0]);

    // ---- phase 1: chunks 0..11 already re-zeroed by phase-0 body ----
    if (i0 >= 52 && i0 < 100) tf[SLOT(i0 - 52)] += c0;
    if (i1 >= 52 && i1 < 100) tf[SLOT(i1 - 52)] += c1;
    if (i2 >= 52 && i2 < 100) tf[SLOT(i2 - 52)] += c2;
    if (i3 >= 52 && i3 < 100) tf[SLOT(i3 - 52)] += c3;
    run<52, CH1, 0, false>(a, col, col[0]);

    out[idx] = (a.W0 + a.W1) / (a.S0 + a.S1);
}

extern "C" void kernel_launch(void* const* d_in, const int* in_sizes, int n_in,
                              void* d_out, int out_size)
{
    const float* spikes = (const float*)d_in[0];  // [512*1024]
    const float* W      = (const float*)d_in[1];  // [256*1024]
    float* out          = (float*)d_out;          // [512*256]

    dendritic_kernel<<<1024, 128>>>(spikes, W, out);
}

// round 11
// speedup vs baseline: 1.0521x; 1.0521x over previous
#include <cuda_runtime.h>

// DendriticLayer: B=512, N_IN=1024, N_OUT=256, T=100, dt=1.
// Event-scatter formulation (R8/R9):
//   delta[ceil(s_j)] += 0.1*K2*w_j*exp((s_j-ceil(s_j))/5)   (private SMEM col)
//   Chat_t = d*Chat_{t-1} + delta_t ;  w_t = 0.9*w_{t-1} + Chat_t  (w = K2*v)
//   e_t = exp2(w_t);  out = (sum t*e_t)/(sum e_t)
// R11 = R9 + (only) two changes: ping-pong LDS prefetch one chunk ahead,
// and dual S/WS accumulators. Zeroing/scatter/consumer order unchanged.

#define CH0 13   // phase-0: 52 steps (t in [0,52))
#define CH1 12   // phase-1: 48 steps (t in [52,100))

__device__ __forceinline__ float ex2(float x) {
    float y;
    asm("ex2.approx.ftz.f32 %0, %1;" : "=f"(y) : "f"(x));
    return y;
}

constexpr float D1f = 0.81873075307798185867f;  // exp(-0.2)
constexpr float K2f = 2.8853900817779268147f;   // 2*log2(e)

struct Acc { float C, w, S0, S1, W0, W1; };

__device__ __forceinline__ void step(Acc& a, float dlt, float tf, int par) {
    a.C = fmaf(a.C, D1f, dlt);
    a.w = fmaf(a.w, 0.9f, a.C);
    const float e = ex2(a.w);
    if (par) { a.S1 += e; a.W1 = fmaf(e, tf, a.W1); }
    else     { a.S0 += e; a.W0 = fmaf(e, tf, a.W0); }
}

template <int T0, int NCH, int K>
__device__ __forceinline__ void run(Acc& a, const float4* __restrict__ col, float4 d4) {
    float4 nxt;
    if constexpr (K + 1 < NCH) nxt = col[(K + 1) * 128];   // prefetch: 21-instr shadow
    step(a, d4.x, (float)(T0 + 4 * K + 0), 0);
    step(a, d4.y, (float)(T0 + 4 * K + 1), 1);
    step(a, d4.z, (float)(T0 + 4 * K + 2), 0);
    step(a, d4.w, (float)(T0 + 4 * K + 3), 1);
    if constexpr (K + 1 < NCH) run<T0, NCH, K + 1>(a, col, nxt);
}

__global__ __launch_bounds__(128)
void dendritic_kernel(const float* __restrict__ spikes,  // [512,1024]
                      const float* __restrict__ W,       // [256,1024]
                      float* __restrict__ out)           // [512,256]
{
    __shared__ float4 tbl[CH0][128];                     // 26.6KB

    const int tid = threadIdx.x;
    const int idx = blockIdx.x * 128 + tid;              // b*256 + o
    const int o   = idx & 255;

    const float4 s4 = reinterpret_cast<const float4*>(spikes)[idx];
    const float4 w4 = reinterpret_cast<const float4*>(W)[257 * o];

    const float e0 = ceilf(s4.x), e1 = ceilf(s4.y), e2 = ceilf(s4.z), e3 = ceilf(s4.w);
    const float kk = 0.1f * K2f;
    const float c0 = kk * w4.x * __expf(0.2f * (s4.x - e0));
    const float c1 = kk * w4.y * __expf(0.2f * (s4.y - e1));
    const float c2 = kk * w4.z * __expf(0.2f * (s4.z - e2));
    const float c3 = kk * w4.w * __expf(0.2f * (s4.w - e3));
    const int i0 = (int)e0, i1 = (int)e1, i2 = (int)e2, i3 = (int)e3;

    float* tf = reinterpret_cast<float*>(tbl);
    const int tb = tid * 4;
    #define SLOT(k) (((k) >> 2) * 512 + tb + ((k) & 3))

    const float4* col = &tbl[0][tid];
    float4 z4 = make_float4(0.f, 0.f, 0.f, 0.f);
    Acc a; a.C = 0.f; a.w = 0.f; a.S0 = 0.f; a.S1 = 0.f; a.W0 = 0.f; a.W1 = 0.f;

    // ---- phase 0: t in [0,52) ----
    #pragma unroll
    for (int c = 0; c < CH0; ++c) tbl[c][tid] = z4;       // 13x STS.128
    if (i0 < 52) tf[SLOT(i0)] += c0;                       // private RMW, race-free
    if (i1 < 52) tf[SLOT(i1)] += c1;
    if (i2 < 52) tf[SLOT(i2)] += c2;
    if (i3 < 52) tf[SLOT(i3)] += c3;
    run<0, CH0, 0>(a, col, col[0]);

    // ---- phase 1: t in [52,100) ----
    #pragma unroll
    for (int c = 0; c < CH1; ++c) tbl[c][tid] = z4;       // 12x STS.128
    if (i0 >= 52 && i0 < 100) tf[SLOT(i0 - 52)] += c0;
    if (i1 >= 52 && i1 < 100) tf[SLOT(i1 - 52)] += c1;
    if (i2 >= 52 && i2 < 100) tf[SLOT(i2 - 52)] += c2;
    if (i3 >= 52 && i3 < 100) tf[SLOT(i3 - 52)] += c3;
    run<52, CH1, 0>(a, col, col[0]);

    out[idx] = (a.W0 + a.W1) / (a.S0 + a.S1);
}

extern "C" void kernel_launch(void* const* d_in, const int* in_sizes, int n_in,
                              void* d_out, int out_size)
{
    const float* spikes = (const float*)d_in[0];  // [512*1024]
    const float* W      = (const float*)d_in[1];  // [256*1024]
    float* out          = (float*)d_out;          // [512*256]

    dendritic_kernel<<<1024, 128>>>(spikes, W, out);
}